// round 2
// baseline (speedup 1.0000x reference)
#include <cuda_runtime.h>
#include <cstdint>

// ROI max pooling, shapes fixed per problem:
//   features: (B=4, C=256, H=50, W=50) float32
//   rois:     (R=256, 5) [b, x1, y1, x2, y2] image coords (0..799)
//             NOTE: reference says int64 but JAX x64 is disabled by default,
//             so the data is almost certainly int32. We sniff the layout at
//             runtime (int64 => all odd 32-bit words are zero high-words).
//   out:      (R=256, C=256, PH=7, PW=7) float32
//
// coords = floor(roi * 0.0625) == roi >> 4 (exact, 0.0625 = 2^-4).
// Adaptive max pool bins: sh = y1 + ph*h/7, eh = y1 + ceil((ph+1)*h/7); same x.
//
// One warp per (roi, c). Lanes cover region columns (rel col = lane, lane+32;
// w <= 50). Per y-bin: coalesced row loads accumulate per-column max in 2
// registers, then a shfl gather (bound = warp-max x-bin width <= 8) produces
// the 7 outputs from lanes 0..6.

#define RP_B  4
#define RP_C  256
#define RP_H  50
#define RP_W  50
#define RP_R  256
#define RP_PH 7
#define RP_PW 7

__global__ __launch_bounds__(256, 8)
void roipool_kernel(const float* __restrict__ feat,
                    const int* __restrict__ rois32,
                    float* __restrict__ out)
{
    const int warp = threadIdx.x >> 5;
    const int lane = threadIdx.x & 31;
    const int c = blockIdx.x * 8 + warp;   // 0..255
    const int r = blockIdx.y;              // 0..255

    // --- dtype sniff: int64 layout has zero high-words at every odd index ---
    int is64 = 0;
    if (lane == 0) {
        int any_nonzero_odd = 0;
        #pragma unroll
        for (int i = 0; i < 16; ++i)
            any_nonzero_odd |= rois32[2 * i + 1];
        is64 = (any_nonzero_odd == 0);
    }
    is64 = __shfl_sync(0xffffffffu, is64, 0);

    // --- decode roi r (all lanes redundantly; tiny, cached) ---
    int b, x1, y1, x2, y2;
    if (is64) {
        const int* rp = rois32 + r * 10;   // low words at even offsets
        b  = rp[0];
        x1 = rp[2] >> 4;
        y1 = rp[4] >> 4;
        x2 = rp[6] >> 4;
        y2 = rp[8] >> 4;
    } else {
        const int* rp = rois32 + r * 5;
        b  = rp[0];
        x1 = rp[1] >> 4;
        y1 = rp[2] >> 4;
        x2 = rp[3] >> 4;
        y2 = rp[4] >> 4;
    }

    const int h = y2 - y1 + 1;             // 1..50
    const int w = x2 - x1 + 1;             // 1..50

    const float* base = feat + (((size_t)b * RP_C + c) * (RP_H * RP_W));

    // x-bin ranges (relative columns), output lane pw = lane (< 7)
    int sw = 0, ew = 0;
    if (lane < RP_PW) {
        sw = (lane * w) / RP_PW;
        ew = ((lane + 1) * w + (RP_PW - 1)) / RP_PW;
    }
    const int binw = ew - sw;
    const int L = __reduce_max_sync(0xffffffffu, binw);  // max x-bin width <= 8

    const bool act_lo = (lane < w);
    const bool act_hi = (lane + 32 < w);

    float* outp = out + (((size_t)r * RP_C + c) * (RP_PH * RP_PW));

    #pragma unroll
    for (int ph = 0; ph < RP_PH; ++ph) {
        const int sh = y1 + (ph * h) / RP_PH;
        const int eh = y1 + (((ph + 1) * h + (RP_PH - 1)) / RP_PH);

        float lo = -__int_as_float(0x7f800000);  // -inf
        float hi = lo;
        const float* row = base + sh * RP_W + x1;
        for (int y = sh; y < eh; ++y) {
            if (act_lo) lo = fmaxf(lo, __ldg(row + lane));
            if (act_hi) hi = fmaxf(hi, __ldg(row + lane + 32));
            row += RP_W;
        }

        // gather per-x-bin max: lane pw covers columns [sw, ew)
        float m = -__int_as_float(0x7f800000);
        for (int i = 0; i < L; ++i) {
            const int k = sw + i;                              // k < w <= 50
            const float va = __shfl_sync(0xffffffffu, lo, k & 31);
            const float vb = __shfl_sync(0xffffffffu, hi, k & 31);
            if (i < binw) m = fmaxf(m, (k < 32) ? va : vb);
        }

        if (lane < RP_PW) outp[ph * RP_PW + lane] = m;
    }
}

extern "C" void kernel_launch(void* const* d_in, const int* in_sizes, int n_in,
                              void* d_out, int out_size)
{
    const float* feat   = (const float*)d_in[0];
    const int*   rois32 = (const int*)d_in[1];
    float*       out    = (float*)d_out;

    dim3 grid(RP_C / 8, RP_R);   // 32 x 256 blocks, 8 warps: warp = (roi, c)
    dim3 block(256);
    roipool_kernel<<<grid, block>>>(feat, rois32, out);
}

// round 4
// speedup vs baseline: 1.4403x; 1.4403x over previous
#include <cuda_runtime.h>
#include <cstdint>

// ROI max pooling (shapes fixed):
//   features: (B=4, C=256, H=50, W=50) fp32;  rois: (R=256, 5) int (see sniff)
//   out: (R=256, C=256, PH=7, PW=7) fp32
//
// Two-kernel plan:
//  1) transpose features -> g_featT[b][p][c]  (p = y*W+x), so channels are
//     contiguous. 32x32 smem tile transpose, both sides coalesced.
//  2) pool: block = (roi, ph), thread = channel. Uniform control flow per
//     block; every load is a fully-used coalesced line across 32 channels.

#define RP_B  4
#define RP_C  256
#define RP_H  50
#define RP_W  50
#define RP_P  (RP_H * RP_W)   // 2500
#define RP_R  256
#define RP_PH 7
#define RP_PW 7

__device__ float g_featT[RP_B * RP_P * RP_C];   // 10.24 MB scratch

// ---------------- transpose: (B,C,P) -> (B,P,C) ----------------
__global__ __launch_bounds__(256)
void transpose_kernel(const float* __restrict__ feat)
{
    __shared__ float tile[32][33];
    const int b  = blockIdx.z;
    const int ct = blockIdx.y;          // channel tile: 0..7
    const int pt = blockIdx.x;          // position tile: 0..78
    const int tx = threadIdx.x & 31;
    const int ty = threadIdx.x >> 5;    // 0..7

    const int p_rd = pt * 32 + tx;
    #pragma unroll
    for (int i = 0; i < 4; ++i) {
        const int c = ct * 32 + ty + i * 8;
        if (p_rd < RP_P)
            tile[ty + i * 8][tx] = feat[((size_t)(b * RP_C + c)) * RP_P + p_rd];
    }
    __syncthreads();

    const int c_wr = ct * 32 + tx;
    #pragma unroll
    for (int i = 0; i < 4; ++i) {
        const int p = pt * 32 + ty + i * 8;
        if (p < RP_P)
            g_featT[((size_t)b * RP_P + p) * RP_C + c_wr] = tile[tx][ty + i * 8];
    }
}

// ---------------- pool: block=(roi, ph), thread=channel ----------------
__global__ __launch_bounds__(256)
void roipool2_kernel(const int* __restrict__ rois32,
                     float* __restrict__ out)
{
    const int r  = blockIdx.x;
    const int ph = blockIdx.y;
    const int c  = threadIdx.x;

    // dtype sniff: int64 layout => all odd 32-bit words are zero high-words.
    int any_nonzero_odd = 0;
    #pragma unroll
    for (int i = 0; i < 16; ++i)
        any_nonzero_odd |= rois32[2 * i + 1];
    const int is64 = (any_nonzero_odd == 0);

    int b, x1, y1, x2, y2;
    if (is64) {
        const int* rp = rois32 + r * 10;       // low words at even offsets
        b = rp[0]; x1 = rp[2] >> 4; y1 = rp[4] >> 4; x2 = rp[6] >> 4; y2 = rp[8] >> 4;
    } else {
        const int* rp = rois32 + r * 5;
        b = rp[0]; x1 = rp[1] >> 4; y1 = rp[2] >> 4; x2 = rp[3] >> 4; y2 = rp[4] >> 4;
    }

    const int h = y2 - y1 + 1;                 // 1..50
    const int w = x2 - x1 + 1;                 // 1..50

    const int sh = y1 + (ph * h) / RP_PH;
    const int eh = y1 + (((ph + 1) * h + (RP_PH - 1)) / RP_PH);

    const float* __restrict__ base = g_featT + ((size_t)b * RP_P) * RP_C + c;
    float* __restrict__ op = out + (((size_t)r * RP_C + c) * RP_PH + ph) * RP_PW;

    const float NEGINF = -__int_as_float(0x7f800000);

    #pragma unroll
    for (int pw = 0; pw < RP_PW; ++pw) {
        const int sw = x1 + (pw * w) / RP_PW;
        const int ew = x1 + (((pw + 1) * w + (RP_PW - 1)) / RP_PW);

        float m = NEGINF;
        for (int y = sh; y < eh; ++y) {
            const float* q = base + (y * RP_W + sw) * RP_C;
            for (int x = sw; x < ew; ++x) {
                m = fmaxf(m, __ldg(q));
                q += RP_C;
            }
        }
        op[pw] = m;
    }
}

extern "C" void kernel_launch(void* const* d_in, const int* in_sizes, int n_in,
                              void* d_out, int out_size)
{
    const float* feat   = (const float*)d_in[0];
    const int*   rois32 = (const int*)d_in[1];
    float*       out    = (float*)d_out;

    dim3 tgrid((RP_P + 31) / 32, RP_C / 32, RP_B);   // 79 x 8 x 4
    transpose_kernel<<<tgrid, 256>>>(feat);

    dim3 pgrid(RP_R, RP_PH);                          // 256 x 7
    roipool2_kernel<<<pgrid, 256>>>(rois32, out);
}